// round 5
// baseline (speedup 1.0000x reference)
#include <cuda_runtime.h>
#include <math.h>

// ---------------------------------------------------------------------------
// LOI: x = clip(im)->CHW ; conv1 = per-channel 9x9 Gaussian (S=2 sigmas)
// iso(b,n) = exp(-0.5*((conv1 - mu_n)/beta_b)^2)/(sqrt(2pi)*beta_b)
// out = 7x7 Gaussian conv (A=3 alphas) of iso (ZERO-padded iso!),
// laid out (A,B,S,C,H,W,N)
// ---------------------------------------------------------------------------

#define HH 512
#define WW 512
#define CC 3
#define SS 2
#define AA 3
#define BB 2
#define NN 8
#define HWPROD (HH * WW)

// Scratch (device-global: allocation-free rule)
__device__ float g_tmp[CC * SS * HWPROD];    // horizontal pass of sigma conv
__device__ float g_conv[CC * SS * HWPROD];   // smoothed field, plane = c*SS+s
__device__ float g_sigma_sep[SS][9];         // separable 1D sigma factors
__device__ float g_alpha_sep[AA][7];         // separable 1D alpha factors

// ---------------------------------------------------------------------------
// Prep: extract exact separable 1D factors.  K = u u^T with
// u[j] = K[center][j] / sqrt(K[center][center]).
// ---------------------------------------------------------------------------
__global__ void prep_kernel(const float* __restrict__ sig,
                            const float* __restrict__ alp) {
    if (threadIdx.x == 0 && blockIdx.x == 0) {
        for (int s = 0; s < SS; s++) {
            float ctr = sig[s * 81 + 4 * 9 + 4];
            float r = 1.0f / sqrtf(ctr);
            for (int j = 0; j < 9; j++)
                g_sigma_sep[s][j] = sig[s * 81 + 4 * 9 + j] * r;
        }
        for (int a = 0; a < AA; a++) {
            float ctr = alp[a * 49 + 3 * 7 + 3];
            float r = 1.0f / sqrtf(ctr);
            for (int j = 0; j < 7; j++)
                g_alpha_sep[a][j] = alp[a * 49 + 3 * 7 + j] * r;
        }
    }
}

// ---------------------------------------------------------------------------
// Stage 1a: horizontal 9-tap over clipped input (HWC layout), zero padded.
// ---------------------------------------------------------------------------
__global__ void sconv_h(const float* __restrict__ im) {
    int x = blockIdx.x * blockDim.x + threadIdx.x;
    int y = blockIdx.y;
    int cs = blockIdx.z;
    int c = cs / SS, s = cs % SS;
    if (x >= WW) return;

    float u[9];
#pragma unroll
    for (int j = 0; j < 9; j++) u[j] = g_sigma_sep[s][j];

    float acc = 0.0f;
#pragma unroll
    for (int j = 0; j < 9; j++) {
        int xx = x + j - 4;
        if (xx >= 0 && xx < WW) {
            float v = im[(y * WW + xx) * CC + c];
            v = fminf(fmaxf(v, 0.0f), 1.0f);
            acc = fmaf(u[j], v, acc);
        }
    }
    g_tmp[cs * HWPROD + y * WW + x] = acc;
}

// ---------------------------------------------------------------------------
// Stage 1b: vertical 9-tap, zero padded -> g_conv.
// ---------------------------------------------------------------------------
__global__ void sconv_v() {
    int x = blockIdx.x * blockDim.x + threadIdx.x;
    int y = blockIdx.y;
    int cs = blockIdx.z;
    int s = cs % SS;
    if (x >= WW) return;

    float u[9];
#pragma unroll
    for (int j = 0; j < 9; j++) u[j] = g_sigma_sep[s][j];

    const float* tp = g_tmp + cs * HWPROD;
    float acc = 0.0f;
#pragma unroll
    for (int j = 0; j < 9; j++) {
        int yy = y + j - 4;
        if (yy >= 0 && yy < HH)
            acc = fmaf(u[j], tp[yy * WW + x], acc);
    }
    g_conv[cs * HWPROD + y * WW + x] = acc;
}

// ---------------------------------------------------------------------------
// Stage 2: fused iso + separable 7x7 alpha conv + transposed vectorized write.
// One CTA = 32x16 output tile for a fixed (c,s,b).  Loop n=0..7, accumulate
// acc[a][n] in registers, emit 2x float4 streaming stores per alpha.
//
// BOUNDARY SEMANTICS: the reference zero-pads ISO (not the smoothed field).
// We store -INF in sConv for out-of-image halo samples; then
// d = (-inf - mu)*invb -> d*d = +inf -> __expf(-inf) = 0, so the iso halo
// is exactly 0 at zero extra cost.
// ---------------------------------------------------------------------------
#define TW 32
#define TH 16
#define HALO 3
#define W2 (TW + 2 * HALO)   // 38
#define H2 (TH + 2 * HALO)   // 22
#define NTHR (TW * TH)       // 512

__global__ __launch_bounds__(NTHR, 2) void loi_kernel(
    const float* __restrict__ bin_centers,
    const float* __restrict__ betas,
    float* __restrict__ out) {
    __shared__ float sConv[H2 * W2];
    __shared__ float sIso[H2 * W2];
    __shared__ float sV[AA][TH * W2];

    const int tx = threadIdx.x, ty = threadIdx.y;
    const int tid = ty * TW + tx;
    const int z = blockIdx.z;
    const int c = z % CC;
    const int s = (z / CC) % SS;
    const int b = z / (CC * SS);
    const int cp = c * SS + s;
    const int gx0 = blockIdx.x * TW, gy0 = blockIdx.y * TH;

    // load smoothed-field tile + halo; OOB sentinel = -INF (=> iso = 0)
    const float* convp = g_conv + cp * HWPROD;
    for (int i = tid; i < H2 * W2; i += NTHR) {
        int ly = i / W2, lx = i - ly * W2;
        int gy = gy0 + ly - HALO, gx = gx0 + lx - HALO;
        float v = -INFINITY;
        if ((unsigned)gy < (unsigned)HH && (unsigned)gx < (unsigned)WW)
            v = convp[gy * WW + gx];
        sConv[i] = v;
    }

    // symmetric half-taps: u[j] == u[6-j] exactly
    float ua[AA][4];
#pragma unroll
    for (int a = 0; a < AA; a++)
#pragma unroll
        for (int j = 0; j < 4; j++) ua[a][j] = g_alpha_sep[a][j];

    float mu[NN];
#pragma unroll
    for (int n = 0; n < NN; n++) mu[n] = bin_centers[n];

    const float beta = betas[b];
    const float invb = 1.0f / beta;
    const float norm = 0.3989422804014327f * invb;  // 1/(sqrt(2pi)*beta)

    float acc[AA][NN];
#pragma unroll
    for (int a = 0; a < AA; a++)
#pragma unroll
        for (int n = 0; n < NN; n++) acc[a][n] = 0.0f;

    __syncthreads();

#pragma unroll
    for (int n = 0; n < NN; n++) {
        // iso plane for this (b, n) over tile + halo; -inf sentinel -> 0
        for (int i = tid; i < H2 * W2; i += NTHR) {
            float d = (sConv[i] - mu[n]) * invb;
            sIso[i] = norm * __expf(-0.5f * d * d);
        }
        __syncthreads();

        // vertical 7-tap (symmetric sums shared across the 3 alphas)
        for (int i = tid; i < TH * W2; i += NTHR) {
            float v0 = sIso[i];
            float v1 = sIso[i + 1 * W2];
            float v2 = sIso[i + 2 * W2];
            float v3 = sIso[i + 3 * W2];
            float v4 = sIso[i + 4 * W2];
            float v5 = sIso[i + 5 * W2];
            float v6 = sIso[i + 6 * W2];
            float w0 = v0 + v6, w1 = v1 + v5, w2 = v2 + v4;
#pragma unroll
            for (int a = 0; a < AA; a++) {
                float r = ua[a][3] * v3;
                r = fmaf(ua[a][0], w0, r);
                r = fmaf(ua[a][1], w1, r);
                r = fmaf(ua[a][2], w2, r);
                sV[a][i] = r;
            }
        }
        __syncthreads();

        // horizontal 7-tap -> register accumulator
        const int base = ty * W2 + tx;
#pragma unroll
        for (int a = 0; a < AA; a++) {
            float h0 = sV[a][base + 0];
            float h1 = sV[a][base + 1];
            float h2 = sV[a][base + 2];
            float h3 = sV[a][base + 3];
            float h4 = sV[a][base + 4];
            float h5 = sV[a][base + 5];
            float h6 = sV[a][base + 6];
            float r = ua[a][3] * h3;
            r = fmaf(ua[a][0], h0 + h6, r);
            r = fmaf(ua[a][1], h1 + h5, r);
            r = fmaf(ua[a][2], h2 + h4, r);
            acc[a][n] = r;
        }
        __syncthreads();  // protect sIso/sV before next n overwrites
    }

    // vectorized transposed write: (A,B,S,C,H,W,N), 8 contiguous N per pixel
    const int gy = gy0 + ty, gx = gx0 + tx;
    const size_t pix = ((size_t)(gy * WW + gx)) * NN;
#pragma unroll
    for (int a = 0; a < AA; a++) {
        const int plane = ((a * BB + b) * SS + s) * CC + c;
        float4* p = (float4*)(out + (size_t)plane * HWPROD * NN + pix);
        __stcs(p + 0, make_float4(acc[a][0], acc[a][1], acc[a][2], acc[a][3]));
        __stcs(p + 1, make_float4(acc[a][4], acc[a][5], acc[a][6], acc[a][7]));
    }
}

// ---------------------------------------------------------------------------
extern "C" void kernel_launch(void* const* d_in, const int* in_sizes, int n_in,
                              void* d_out, int out_size) {
    (void)in_sizes; (void)n_in; (void)out_size;
    const float* im    = (const float*)d_in[0];  // (512,512,3)
    const float* sig   = (const float*)d_in[1];  // (2,9,9)
    const float* alp   = (const float*)d_in[2];  // (3,7,7)
    const float* binc  = (const float*)d_in[3];  // (8,)
    const float* betas = (const float*)d_in[4];  // (2,)
    float* out = (float*)d_out;                  // (3,2,2,3,512,512,8)

    prep_kernel<<<1, 32>>>(sig, alp);
    sconv_h<<<dim3(2, HH, CC * SS), 256>>>(im);
    sconv_v<<<dim3(2, HH, CC * SS), 256>>>();
    loi_kernel<<<dim3(WW / TW, HH / TH, CC * SS * BB), dim3(TW, TH)>>>(
        binc, betas, out);
}

// round 9
// speedup vs baseline: 1.2061x; 1.2061x over previous
#include <cuda_runtime.h>
#include <math.h>

// ---------------------------------------------------------------------------
// LOI: x = clip(im)->CHW ; conv1 = per-channel 9x9 Gaussian (S=2 sigmas)
// iso(b,n) = exp(-0.5*((conv1 - mu_n)/beta_b)^2)/(sqrt(2pi)*beta_b)
// out = 7x7 Gaussian conv (A=3 alphas) of iso (zero-padded ISO),
// laid out (A,B,S,C,H,W,N)
// ---------------------------------------------------------------------------

#define HH 512
#define WW 512
#define CC 3
#define SS 2
#define AA 3
#define BB 2
#define NN 8
#define HWPROD (HH * WW)

__device__ float g_conv[CC * SS * HWPROD];   // smoothed field, plane = c*SS+s
__device__ float g_sigma_sep[SS][9];         // separable 1D sigma factors
__device__ float g_alpha_sep[AA][7];         // separable 1D alpha factors

// ---------------------------------------------------------------------------
// Prep: exact separable factors, u[j] = K[ctr][j] / sqrt(K[ctr][ctr]).
// ---------------------------------------------------------------------------
__global__ void prep_kernel(const float* __restrict__ sig,
                            const float* __restrict__ alp) {
    if (threadIdx.x == 0 && blockIdx.x == 0) {
        for (int s = 0; s < SS; s++) {
            float r = 1.0f / sqrtf(sig[s * 81 + 4 * 9 + 4]);
            for (int j = 0; j < 9; j++)
                g_sigma_sep[s][j] = sig[s * 81 + 4 * 9 + j] * r;
        }
        for (int a = 0; a < AA; a++) {
            float r = 1.0f / sqrtf(alp[a * 49 + 3 * 7 + 3]);
            for (int j = 0; j < 7; j++)
                g_alpha_sep[a][j] = alp[a * 49 + 3 * 7 + j] * r;
        }
    }
}

// ---------------------------------------------------------------------------
// Stage 1 (fused): clipped input -> 9x9 Gaussian smooth, both sigmas in one
// CTA sharing the image tile.  Tile 32x32 out, halo 4 -> 40x40 region.
// ---------------------------------------------------------------------------
__global__ __launch_bounds__(256) void stage1_kernel(const float* __restrict__ im) {
    __shared__ float sIm[40 * 40];
    __shared__ float sH[SS][40 * 40];
    __shared__ float sSig[SS][9];

    const int tid = threadIdx.x;
    const int c = blockIdx.z;
    const int gx0 = blockIdx.x * 32 - 4, gy0 = blockIdx.y * 32 - 4;

    if (tid < SS * 9) sSig[tid / 9][tid % 9] = g_sigma_sep[tid / 9][tid % 9];

    for (int i = tid; i < 40 * 40; i += 256) {
        int ly = i / 40, lx = i - ly * 40;
        int gy = gy0 + ly, gx = gx0 + lx;
        float v = 0.0f;
        if ((unsigned)gy < (unsigned)HH && (unsigned)gx < (unsigned)WW) {
            v = im[(gy * WW + gx) * CC + c];
            v = fminf(fmaxf(v, 0.0f), 1.0f);
        }
        sIm[i] = v;
    }
    __syncthreads();

    // horizontal 9-tap (symmetric): rows 0..39, out cols 0..31
    for (int i = tid; i < 40 * 32; i += 256) {
        int ly = i / 32, ox = i - ly * 32;
        int base = ly * 40 + ox;
        float p0 = sIm[base] + sIm[base + 8];
        float p1 = sIm[base + 1] + sIm[base + 7];
        float p2 = sIm[base + 2] + sIm[base + 6];
        float p3 = sIm[base + 3] + sIm[base + 5];
        float ctr = sIm[base + 4];
#pragma unroll
        for (int s = 0; s < SS; s++) {
            float r = sSig[s][4] * ctr;
            r = fmaf(sSig[s][0], p0, r);
            r = fmaf(sSig[s][1], p1, r);
            r = fmaf(sSig[s][2], p2, r);
            r = fmaf(sSig[s][3], p3, r);
            sH[s][ly * 40 + ox] = r;
        }
    }
    __syncthreads();

    // vertical 9-tap (symmetric): out 32x32
    for (int i = tid; i < 32 * 32; i += 256) {
        int oy = i / 32, ox = i - oy * 32;
        int gy = gy0 + 4 + oy, gx = gx0 + 4 + ox;
#pragma unroll
        for (int s = 0; s < SS; s++) {
            const float* hp = &sH[s][oy * 40 + ox];
            float p0 = hp[0 * 40] + hp[8 * 40];
            float p1 = hp[1 * 40] + hp[7 * 40];
            float p2 = hp[2 * 40] + hp[6 * 40];
            float p3 = hp[3 * 40] + hp[5 * 40];
            float r = sSig[s][4] * hp[4 * 40];
            r = fmaf(sSig[s][0], p0, r);
            r = fmaf(sSig[s][1], p1, r);
            r = fmaf(sSig[s][2], p2, r);
            r = fmaf(sSig[s][3], p3, r);
            g_conv[(c * SS + s) * HWPROD + gy * WW + gx] = r;
        }
    }
}

// ---------------------------------------------------------------------------
// Stage 2: fused iso + separable 7x7 alpha conv, smem-minimal.
//   Tile: 32x16 outputs per CTA for fixed (c,s,b).  384 threads.
//   Vertical role (tid<152): (col 0..37, seg 0..3): exp inline from sConv,
//     symmetric 7-tap down columns for 4 rows x 3 alphas -> sV (dbl-buffered).
//   Horizontal role (all 384): (a, row, 4-px run): float4 window reads,
//     symmetric 7-tap, acc[4px][8n] in regs, final 2x float4 stcs per px.
// OOB sentinel in sConv = -INF  =>  iso halo == 0 exactly (zero-padded iso).
// ---------------------------------------------------------------------------
#define TW 32
#define TH 16
#define HALO 3
#define W2 (TW + 2 * HALO)   // 38
#define H2 (TH + 2 * HALO)   // 22
#define VSTRIDE 40
#define NTHR 384

__global__ __launch_bounds__(NTHR, 2) void loi_kernel(
    const float* __restrict__ bin_centers,
    const float* __restrict__ betas,
    float* __restrict__ out) {
    __shared__ __align__(16) float sConv[H2 * W2];
    __shared__ __align__(16) float sV[2][AA][TH * VSTRIDE];
    __shared__ float sTap[AA * 4];
    __shared__ float sMu[NN];
    __shared__ float sBeta[2];  // invb, norm

    const int tid = threadIdx.x;
    const int z = blockIdx.z;
    const int c = z % CC;
    const int s = (z / CC) % SS;
    const int b = z / (CC * SS);
    const int gx0 = blockIdx.x * TW, gy0 = blockIdx.y * TH;

    if (tid < AA * 4) sTap[tid] = g_alpha_sep[tid >> 2][tid & 3];
    if (tid < NN) sMu[tid] = bin_centers[tid];
    if (tid == NN) {
        float be = betas[b];
        sBeta[0] = 1.0f / be;
        sBeta[1] = 0.3989422804014327f / be;
    }

    // smoothed-field tile + halo; OOB sentinel -INF => iso = 0
    const float* convp = g_conv + (c * SS + s) * HWPROD;
    for (int i = tid; i < H2 * W2; i += NTHR) {
        int ly = i / W2, lx = i - ly * W2;
        int gy = gy0 + ly - HALO, gx = gx0 + lx - HALO;
        float v = -INFINITY;
        if ((unsigned)gy < (unsigned)HH && (unsigned)gx < (unsigned)WW)
            v = convp[gy * WW + gx];
        sConv[i] = v;
    }
    __syncthreads();

    // roles
    const bool vact = tid < W2 * 4;            // 152 vertical workers
    const int vcol = tid % W2;
    const int r0 = (tid / W2) * 4;             // first output row of segment
    const int a_h = tid / (TH * 8);            // horizontal alpha
    const int rr = tid % (TH * 8);
    const int row_h = rr >> 3;
    const int x0 = (rr & 7) * 4;

    const float ua0 = sTap[a_h * 4 + 0];
    const float ua1 = sTap[a_h * 4 + 1];
    const float ua2 = sTap[a_h * 4 + 2];
    const float ua3 = sTap[a_h * 4 + 3];
    const float invb = sBeta[0];
    const float norm = sBeta[1];

    float acc[4][NN];

#pragma unroll
    for (int n = 0; n < NN; n++) {
        // ---- vertical: iso inline + symmetric 7-tap over columns ----
        if (vact) {
            const float mu_n = sMu[n];
            float iso[10];
#pragma unroll
            for (int k = 0; k < 10; k++) {
                float cv = sConv[(r0 + k) * W2 + vcol];
                float d = (cv - mu_n) * invb;
                iso[k] = norm * __expf(-0.5f * d * d);
            }
            float* vb = &sV[n & 1][0][0];
#pragma unroll
            for (int r = 0; r < 4; r++) {
                float w0 = iso[r] + iso[r + 6];
                float w1 = iso[r + 1] + iso[r + 5];
                float w2 = iso[r + 2] + iso[r + 4];
                float v3 = iso[r + 3];
#pragma unroll
                for (int a = 0; a < AA; a++) {
                    float rv = sTap[a * 4 + 3] * v3;
                    rv = fmaf(sTap[a * 4 + 0], w0, rv);
                    rv = fmaf(sTap[a * 4 + 1], w1, rv);
                    rv = fmaf(sTap[a * 4 + 2], w2, rv);
                    vb[a * (TH * VSTRIDE) + (r0 + r) * VSTRIDE + vcol] = rv;
                }
            }
        }
        __syncthreads();

        // ---- horizontal: 4-px run, symmetric 7-tap, vector window ----
        const float* vp = &sV[n & 1][a_h][row_h * VSTRIDE + x0];
        float4 q0 = *(const float4*)vp;
        float4 q1 = *(const float4*)(vp + 4);
        float2 q2 = *(const float2*)(vp + 8);
        float h0 = q0.x, h1 = q0.y, h2 = q0.z, h3 = q0.w;
        float h4 = q1.x, h5 = q1.y, h6 = q1.z, h7 = q1.w;
        float h8 = q2.x, h9 = q2.y;

        acc[0][n] = fmaf(ua0, h0 + h6, fmaf(ua1, h1 + h5, fmaf(ua2, h2 + h4, ua3 * h3)));
        acc[1][n] = fmaf(ua0, h1 + h7, fmaf(ua1, h2 + h6, fmaf(ua2, h3 + h5, ua3 * h4)));
        acc[2][n] = fmaf(ua0, h2 + h8, fmaf(ua1, h3 + h7, fmaf(ua2, h4 + h6, ua3 * h5)));
        acc[3][n] = fmaf(ua0, h3 + h9, fmaf(ua1, h4 + h8, fmaf(ua2, h5 + h7, ua3 * h6)));
        // no trailing barrier: sV is double-buffered, next n writes the other buf
    }

    // ---- vectorized transposed write: (A,B,S,C,H,W,N) ----
    const int gy = gy0 + row_h, gx = gx0 + x0;
    const int plane = ((a_h * BB + b) * SS + s) * CC + c;
    float* op = out + (size_t)plane * (size_t)HWPROD * NN +
                ((size_t)(gy * WW + gx)) * NN;
#pragma unroll
    for (int px = 0; px < 4; px++) {
        __stcs((float4*)(op + px * NN),
               make_float4(acc[px][0], acc[px][1], acc[px][2], acc[px][3]));
        __stcs((float4*)(op + px * NN + 4),
               make_float4(acc[px][4], acc[px][5], acc[px][6], acc[px][7]));
    }
}

// ---------------------------------------------------------------------------
extern "C" void kernel_launch(void* const* d_in, const int* in_sizes, int n_in,
                              void* d_out, int out_size) {
    (void)in_sizes; (void)n_in; (void)out_size;
    const float* im    = (const float*)d_in[0];  // (512,512,3)
    const float* sig   = (const float*)d_in[1];  // (2,9,9)
    const float* alp   = (const float*)d_in[2];  // (3,7,7)
    const float* binc  = (const float*)d_in[3];  // (8,)
    const float* betas = (const float*)d_in[4];  // (2,)
    float* out = (float*)d_out;                  // (3,2,2,3,512,512,8)

    prep_kernel<<<1, 32>>>(sig, alp);
    stage1_kernel<<<dim3(16, 16, CC), 256>>>(im);
    loi_kernel<<<dim3(WW / TW, HH / TH, CC * SS * BB), NTHR>>>(binc, betas, out);
}

// round 11
// speedup vs baseline: 1.4078x; 1.1672x over previous
#include <cuda_runtime.h>
#include <math.h>

// ---------------------------------------------------------------------------
// LOI: x = clip(im)->CHW ; conv1 = per-channel 9x9 Gaussian (S=2 sigmas)
// iso(b,n) = exp(-0.5*((conv1 - mu_n)/beta_b)^2)/(sqrt(2pi)*beta_b)
// out = 7x7 Gaussian conv (A=3 alphas) of iso (zero-padded ISO),
// laid out (A,B,S,C,H,W,N)
// ---------------------------------------------------------------------------

#define HH 512
#define WW 512
#define CC 3
#define SS 2
#define AA 3
#define BB 2
#define NN 8
#define HWPROD (HH * WW)

__device__ float g_conv[CC * SS * HWPROD];   // smoothed field, plane = c*SS+s

// ---------------------------------------------------------------------------
// Stage 1 (fused): clipped input -> 9x9 Gaussian smooth, both sigmas in one
// CTA sharing the image tile.  Tile 32x32 out, halo 4 -> 40x40 region.
// Sigma separable taps derived per-CTA: u[j] = K[ctr][j]/sqrt(K[ctr][ctr]).
// ---------------------------------------------------------------------------
__global__ __launch_bounds__(256) void stage1_kernel(const float* __restrict__ im,
                                                     const float* __restrict__ sig) {
    __shared__ float sIm[40 * 40];
    __shared__ float sH[SS][40 * 40];
    __shared__ float sSig[SS][9];

    const int tid = threadIdx.x;
    const int c = blockIdx.z;
    const int gx0 = blockIdx.x * 32 - 4, gy0 = blockIdx.y * 32 - 4;

    if (tid < SS) {  // one thread per sigma derives its 9 taps
        float r = rsqrtf(sig[tid * 81 + 4 * 9 + 4]);
        for (int j = 0; j < 9; j++)
            sSig[tid][j] = sig[tid * 81 + 4 * 9 + j] * r;
    }

    for (int i = tid; i < 40 * 40; i += 256) {
        int ly = i / 40, lx = i - ly * 40;
        int gy = gy0 + ly, gx = gx0 + lx;
        float v = 0.0f;
        if ((unsigned)gy < (unsigned)HH && (unsigned)gx < (unsigned)WW) {
            v = im[(gy * WW + gx) * CC + c];
            v = fminf(fmaxf(v, 0.0f), 1.0f);
        }
        sIm[i] = v;
    }
    __syncthreads();

    // horizontal 9-tap (symmetric): rows 0..39, out cols 0..31
    for (int i = tid; i < 40 * 32; i += 256) {
        int ly = i / 32, ox = i - ly * 32;
        int base = ly * 40 + ox;
        float p0 = sIm[base] + sIm[base + 8];
        float p1 = sIm[base + 1] + sIm[base + 7];
        float p2 = sIm[base + 2] + sIm[base + 6];
        float p3 = sIm[base + 3] + sIm[base + 5];
        float ctr = sIm[base + 4];
#pragma unroll
        for (int s = 0; s < SS; s++) {
            float r = sSig[s][4] * ctr;
            r = fmaf(sSig[s][0], p0, r);
            r = fmaf(sSig[s][1], p1, r);
            r = fmaf(sSig[s][2], p2, r);
            r = fmaf(sSig[s][3], p3, r);
            sH[s][ly * 40 + ox] = r;
        }
    }
    __syncthreads();

    // vertical 9-tap (symmetric): out 32x32
    for (int i = tid; i < 32 * 32; i += 256) {
        int oy = i / 32, ox = i - oy * 32;
        int gy = gy0 + 4 + oy, gx = gx0 + 4 + ox;
#pragma unroll
        for (int s = 0; s < SS; s++) {
            const float* hp = &sH[s][oy * 40 + ox];
            float p0 = hp[0 * 40] + hp[8 * 40];
            float p1 = hp[1 * 40] + hp[7 * 40];
            float p2 = hp[2 * 40] + hp[6 * 40];
            float p3 = hp[3 * 40] + hp[5 * 40];
            float r = sSig[s][4] * hp[4 * 40];
            r = fmaf(sSig[s][0], p0, r);
            r = fmaf(sSig[s][1], p1, r);
            r = fmaf(sSig[s][2], p2, r);
            r = fmaf(sSig[s][3], p3, r);
            g_conv[(c * SS + s) * HWPROD + gy * WW + gx] = r;
        }
    }
}

// ---------------------------------------------------------------------------
// Stage 2: fused iso + separable 7x7 alpha conv.
//   Tile 32x16 per CTA, fixed (c,s,b). 384 threads, 3 CTAs/SM.
//   n-loop runs in 4 PAIRS (n=2p, 2p+1):
//     vertical: 304 threads (2 n x 152 (col,seg) tasks), exp inline from
//       sConv, symmetric 7-tap down columns -> sV[n&3] (4-slot ring).
//       Ring needs no trailing barrier: pair p+1's writes only touch slots
//       read by pair p-1, and the pair-p sync separates them.
//     horizontal: all 384 (a, row, 4-px run), vector window reads,
//       symmetric 7-tap -> acc[4px][4n]; stores flushed after each half.
// OOB sentinel in sConv = -INF  =>  iso halo == 0 exactly (zero-padded iso).
// ---------------------------------------------------------------------------
#define TW 32
#define TH 16
#define HALO 3
#define W2 (TW + 2 * HALO)   // 38
#define H2 (TH + 2 * HALO)   // 22
#define VSTRIDE 40
#define NTHR 384

__global__ __launch_bounds__(NTHR, 3) void loi_kernel(
    const float* __restrict__ alp,
    const float* __restrict__ bin_centers,
    const float* __restrict__ betas,
    float* __restrict__ out) {
    __shared__ __align__(16) float sConv[H2 * W2];
    __shared__ __align__(16) float sV[4][AA][TH * VSTRIDE];
    __shared__ float sTap[AA * 4];
    __shared__ float sMu[NN];
    __shared__ float sBeta[2];  // invb, norm

    const int tid = threadIdx.x;
    const int z = blockIdx.z;
    const int c = z % CC;
    const int s = (z / CC) % SS;
    const int b = z / (CC * SS);
    const int gx0 = blockIdx.x * TW, gy0 = blockIdx.y * TH;

    if (tid < AA) {  // one thread per alpha derives its symmetric half-taps
        float r = rsqrtf(alp[tid * 49 + 3 * 7 + 3]);
        for (int j = 0; j < 4; j++)
            sTap[tid * 4 + j] = alp[tid * 49 + 3 * 7 + j] * r;
    }
    if (tid >= 16 && tid < 16 + NN) sMu[tid - 16] = bin_centers[tid - 16];
    if (tid == 24) {
        float be = betas[b];
        sBeta[0] = 1.0f / be;
        sBeta[1] = 0.3989422804014327f / be;
    }

    // smoothed-field tile + halo; OOB sentinel -INF => iso = 0
    const float* convp = g_conv + (c * SS + s) * HWPROD;
    for (int i = tid; i < H2 * W2; i += NTHR) {
        int ly = i / W2, lx = i - ly * W2;
        int gy = gy0 + ly - HALO, gx = gx0 + lx - HALO;
        float v = -INFINITY;
        if ((unsigned)gy < (unsigned)HH && (unsigned)gx < (unsigned)WW)
            v = convp[gy * WW + gx];
        sConv[i] = v;
    }
    __syncthreads();

    // roles
    const bool vact = tid < 2 * W2 * 4;        // 304 vertical workers
    const int vn = tid / (W2 * 4);             // which n of the pair (0/1)
    const int vt = tid % (W2 * 4);
    const int vcol = vt % W2;
    const int r0 = (vt / W2) * 4;              // first output row of segment
    const int a_h = tid / (TH * 8);            // horizontal alpha
    const int rr = tid % (TH * 8);
    const int row_h = rr >> 3;
    const int x0 = (rr & 7) * 4;

    const float ua0 = sTap[a_h * 4 + 0];
    const float ua1 = sTap[a_h * 4 + 1];
    const float ua2 = sTap[a_h * 4 + 2];
    const float ua3 = sTap[a_h * 4 + 3];
    const float invb = sBeta[0];
    const float norm = sBeta[1];

    // output base for this thread's 4-px run
    const int gy = gy0 + row_h, gx = gx0 + x0;
    const int plane = ((a_h * BB + b) * SS + s) * CC + c;
    float* op = out + (size_t)plane * (size_t)HWPROD * NN +
                ((size_t)(gy * WW + gx)) * NN;

    float acc[4][4];

#pragma unroll
    for (int p = 0; p < 4; p++) {
        // ---- vertical: iso inline + symmetric 7-tap, pair (2p, 2p+1) ----
        if (vact) {
            const int n = 2 * p + vn;
            const float mu_n = sMu[n];
            float iso[10];
#pragma unroll
            for (int k = 0; k < 10; k++) {
                float cv = sConv[(r0 + k) * W2 + vcol];
                float d = (cv - mu_n) * invb;
                iso[k] = norm * __expf(-0.5f * d * d);
            }
            float* vb = &sV[n & 3][0][0];
#pragma unroll
            for (int r = 0; r < 4; r++) {
                float w0 = iso[r] + iso[r + 6];
                float w1 = iso[r + 1] + iso[r + 5];
                float w2 = iso[r + 2] + iso[r + 4];
                float v3 = iso[r + 3];
#pragma unroll
                for (int a = 0; a < AA; a++) {
                    float rv = sTap[a * 4 + 3] * v3;
                    rv = fmaf(sTap[a * 4 + 0], w0, rv);
                    rv = fmaf(sTap[a * 4 + 1], w1, rv);
                    rv = fmaf(sTap[a * 4 + 2], w2, rv);
                    vb[a * (TH * VSTRIDE) + (r0 + r) * VSTRIDE + vcol] = rv;
                }
            }
        }
        __syncthreads();

        // ---- horizontal: both n of the pair ----
#pragma unroll
        for (int k = 0; k < 2; k++) {
            const int n = 2 * p + k;
            const int ai = n & 3;  // accumulator slot within half
            const float* vp = &sV[n & 3][a_h][row_h * VSTRIDE + x0];
            float4 q0 = *(const float4*)vp;
            float4 q1 = *(const float4*)(vp + 4);
            float2 q2 = *(const float2*)(vp + 8);
            float h0 = q0.x, h1 = q0.y, h2 = q0.z, h3 = q0.w;
            float h4 = q1.x, h5 = q1.y, h6 = q1.z, h7 = q1.w;
            float h8 = q2.x, h9 = q2.y;

            acc[0][ai] = fmaf(ua0, h0 + h6, fmaf(ua1, h1 + h5, fmaf(ua2, h2 + h4, ua3 * h3)));
            acc[1][ai] = fmaf(ua0, h1 + h7, fmaf(ua1, h2 + h6, fmaf(ua2, h3 + h5, ua3 * h4)));
            acc[2][ai] = fmaf(ua0, h2 + h8, fmaf(ua1, h3 + h7, fmaf(ua2, h4 + h6, ua3 * h5)));
            acc[3][ai] = fmaf(ua0, h3 + h9, fmaf(ua1, h4 + h8, fmaf(ua2, h5 + h7, ua3 * h6)));
        }

        // ---- flush after each half of n (keeps acc at 16 regs) ----
        if (p == 1 || p == 3) {
            const int off = (p == 1) ? 0 : 4;
#pragma unroll
            for (int px = 0; px < 4; px++)
                __stcs((float4*)(op + px * NN + off),
                       make_float4(acc[px][0], acc[px][1], acc[px][2], acc[px][3]));
        }
        // no trailing barrier: 4-slot sV ring (see header comment)
    }
}

// ---------------------------------------------------------------------------
extern "C" void kernel_launch(void* const* d_in, const int* in_sizes, int n_in,
                              void* d_out, int out_size) {
    (void)in_sizes; (void)n_in; (void)out_size;
    const float* im    = (const float*)d_in[0];  // (512,512,3)
    const float* sig   = (const float*)d_in[1];  // (2,9,9)
    const float* alp   = (const float*)d_in[2];  // (3,7,7)
    const float* binc  = (const float*)d_in[3];  // (8,)
    const float* betas = (const float*)d_in[4];  // (2,)
    float* out = (float*)d_out;                  // (3,2,2,3,512,512,8)

    stage1_kernel<<<dim3(16, 16, CC), 256>>>(im, sig);
    loi_kernel<<<dim3(WW / TW, HH / TH, CC * SS * BB), NTHR>>>(alp, binc, betas, out);
}

// round 15
// speedup vs baseline: 1.5762x; 1.1197x over previous
#include <cuda_runtime.h>
#include <cuda_fp16.h>
#include <math.h>

// ---------------------------------------------------------------------------
// LOI: x = clip(im)->CHW ; conv1 = per-channel 9x9 Gaussian (S=2 sigmas)
// iso(b,n) = exp(-0.5*((conv1 - mu_n)/beta_b)^2)/(sqrt(2pi)*beta_b)
// out = 7x7 Gaussian conv (A=3 alphas) of iso (zero-padded ISO),
// laid out (A,B,S,C,H,W,N)
// ---------------------------------------------------------------------------

#define HH 512
#define WW 512
#define CC 3
#define SS 2
#define AA 3
#define BB 2
#define NN 8
#define HWPROD (HH * WW)

__device__ float g_conv[CC * SS * HWPROD];   // smoothed field, plane = c*SS+s

// ---------------------------------------------------------------------------
// Stage 1 (fused): clipped input -> 9x9 Gaussian smooth, both sigmas in one
// CTA sharing the image tile.  Tile 32x32 out, halo 4 -> 40x40 region.
// ---------------------------------------------------------------------------
__global__ __launch_bounds__(256) void stage1_kernel(const float* __restrict__ im,
                                                     const float* __restrict__ sig) {
    __shared__ float sIm[40 * 40];
    __shared__ float sH[SS][40 * 40];
    __shared__ float sSig[SS][9];

    const int tid = threadIdx.x;
    const int c = blockIdx.z;
    const int gx0 = blockIdx.x * 32 - 4, gy0 = blockIdx.y * 32 - 4;

    if (tid < SS) {  // one thread per sigma derives its 9 taps
        float r = rsqrtf(sig[tid * 81 + 4 * 9 + 4]);
        for (int j = 0; j < 9; j++)
            sSig[tid][j] = sig[tid * 81 + 4 * 9 + j] * r;
    }

    for (int i = tid; i < 40 * 40; i += 256) {
        int ly = i / 40, lx = i - ly * 40;
        int gy = gy0 + ly, gx = gx0 + lx;
        float v = 0.0f;
        if ((unsigned)gy < (unsigned)HH && (unsigned)gx < (unsigned)WW) {
            v = im[(gy * WW + gx) * CC + c];
            v = fminf(fmaxf(v, 0.0f), 1.0f);
        }
        sIm[i] = v;
    }
    __syncthreads();

    for (int i = tid; i < 40 * 32; i += 256) {
        int ly = i / 32, ox = i - ly * 32;
        int base = ly * 40 + ox;
        float p0 = sIm[base] + sIm[base + 8];
        float p1 = sIm[base + 1] + sIm[base + 7];
        float p2 = sIm[base + 2] + sIm[base + 6];
        float p3 = sIm[base + 3] + sIm[base + 5];
        float ctr = sIm[base + 4];
#pragma unroll
        for (int s = 0; s < SS; s++) {
            float r = sSig[s][4] * ctr;
            r = fmaf(sSig[s][0], p0, r);
            r = fmaf(sSig[s][1], p1, r);
            r = fmaf(sSig[s][2], p2, r);
            r = fmaf(sSig[s][3], p3, r);
            sH[s][ly * 40 + ox] = r;
        }
    }
    __syncthreads();

    for (int i = tid; i < 32 * 32; i += 256) {
        int oy = i / 32, ox = i - oy * 32;
        int gy = gy0 + 4 + oy, gx = gx0 + 4 + ox;
#pragma unroll
        for (int s = 0; s < SS; s++) {
            const float* hp = &sH[s][oy * 40 + ox];
            float p0 = hp[0 * 40] + hp[8 * 40];
            float p1 = hp[1 * 40] + hp[7 * 40];
            float p2 = hp[2 * 40] + hp[6 * 40];
            float p3 = hp[3 * 40] + hp[5 * 40];
            float r = sSig[s][4] * hp[4 * 40];
            r = fmaf(sSig[s][0], p0, r);
            r = fmaf(sSig[s][1], p1, r);
            r = fmaf(sSig[s][2], p2, r);
            r = fmaf(sSig[s][3], p3, r);
            g_conv[(c * SS + s) * HWPROD + gy * WW + gx] = r;
        }
    }
}

// ---------------------------------------------------------------------------
// Stage 2: fused iso + separable 7x7 alpha conv, byte-minimal.
//   Tile 32x16 per CTA, fixed (c,s,b). 384 threads, 3 CTAs/SM, 2 barriers.
//   VERTICAL (tid<304, thread=(n=tid&7, col=tid>>3)): load the whole 22-row
//     sConv column ONCE (warp reads are 16B broadcasts), 22 inline exps,
//     slide the symmetric 7-tap window down all 16 rows, emit fp16 vsums
//     for 3 alphas into sVh[n] (8 n-planes, stride padded for bank spread).
//   HORIZONTAL (all 384, thread=(alpha,row,4-px run)): loop all 8 n,
//     5x half2 window loads -> fp32 symmetric 7-tap -> acc[4px][4n],
//     float4 streaming stores flushed at n=3 and n=7.
// OOB sentinel in sConv = -INF  =>  iso halo == 0 exactly (zero-padded iso).
// fp16 sV: |vsum|<=8, quantization RMS ~2.8e-4, smoothed by the horizontal
// conv -> final rel_err ~1.5e-4, well under the 1e-3 gate.
// ---------------------------------------------------------------------------
#define TW 32
#define TH 16
#define HALO 3
#define W2 (TW + 2 * HALO)   // 38
#define H2 (TH + 2 * HALO)   // 22
#define HSTRIDE 42           // halves per row (21 words, odd -> bank rotate)
#define APLANE (TH * HSTRIDE)        // 672 halves per alpha plane
#define NPLANE (AA * APLANE + 2)     // 2018 halves; 1009 words, 17k mod 32 distinct
#define NTHR 384

__global__ __launch_bounds__(NTHR, 3) void loi_kernel(
    const float* __restrict__ alp,
    const float* __restrict__ bin_centers,
    const float* __restrict__ betas,
    float* __restrict__ out) {
    __shared__ __align__(16) float sConv[H2 * W2];
    __shared__ __align__(16) __half sVh[NN * NPLANE];
    __shared__ float sTap[AA * 4];
    __shared__ float sMu[NN];
    __shared__ float sBeta[2];  // invb, norm

    const int tid = threadIdx.x;
    const int z = blockIdx.z;
    const int c = z % CC;
    const int s = (z / CC) % SS;
    const int b = z / (CC * SS);
    const int gx0 = blockIdx.x * TW, gy0 = blockIdx.y * TH;

    if (tid < AA) {  // one thread per alpha derives its symmetric half-taps
        float r = rsqrtf(alp[tid * 49 + 3 * 7 + 3]);
        for (int j = 0; j < 4; j++)
            sTap[tid * 4 + j] = alp[tid * 49 + 3 * 7 + j] * r;
    }
    if (tid >= 16 && tid < 16 + NN) sMu[tid - 16] = bin_centers[tid - 16];
    if (tid == 24) {
        float be = betas[b];
        sBeta[0] = 1.0f / be;
        sBeta[1] = 0.3989422804014327f / be;
    }

    // smoothed-field tile + halo; OOB sentinel -INF => iso = 0
    const float* convp = g_conv + (c * SS + s) * HWPROD;
    for (int i = tid; i < H2 * W2; i += NTHR) {
        int ly = i / W2, lx = i - ly * W2;
        int gy = gy0 + ly - HALO, gx = gx0 + lx - HALO;
        float v = -INFINITY;
        if ((unsigned)gy < (unsigned)HH && (unsigned)gx < (unsigned)WW)
            v = convp[gy * WW + gx];
        sConv[i] = v;
    }
    __syncthreads();

    const float invb = sBeta[0];
    const float norm = sBeta[1];

    // ---- VERTICAL: whole column per thread, all n at once ----
    if (tid < NN * W2) {                 // 304 workers
        const int n = tid & 7;
        const int col = tid >> 3;        // 0..37
        const float mu_n = sMu[n];

        float iso[H2];
#pragma unroll
        for (int k = 0; k < H2; k++) {
            float cv = sConv[k * W2 + col];
            float d = (cv - mu_n) * invb;
            iso[k] = norm * __expf(-0.5f * d * d);
        }

        __half* vb = sVh + n * NPLANE + col;
#pragma unroll
        for (int r = 0; r < TH; r++) {
            float w0 = iso[r] + iso[r + 6];
            float w1 = iso[r + 1] + iso[r + 5];
            float w2 = iso[r + 2] + iso[r + 4];
            float v3 = iso[r + 3];
#pragma unroll
            for (int a = 0; a < AA; a++) {
                float rv = sTap[a * 4 + 3] * v3;
                rv = fmaf(sTap[a * 4 + 0], w0, rv);
                rv = fmaf(sTap[a * 4 + 1], w1, rv);
                rv = fmaf(sTap[a * 4 + 2], w2, rv);
                vb[a * APLANE + r * HSTRIDE] = __float2half_rn(rv);
            }
        }
    }
    __syncthreads();

    // ---- HORIZONTAL: (alpha, row, 4-px run), all 8 n ----
    const int a_h = tid / (TH * 8);
    const int rr = tid % (TH * 8);
    const int row_h = rr >> 3;
    const int x0 = (rr & 7) * 4;

    const float ua0 = sTap[a_h * 4 + 0];
    const float ua1 = sTap[a_h * 4 + 1];
    const float ua2 = sTap[a_h * 4 + 2];
    const float ua3 = sTap[a_h * 4 + 3];

    const int gy = gy0 + row_h, gx = gx0 + x0;
    const int plane = ((a_h * BB + b) * SS + s) * CC + c;
    float* op = out + (size_t)plane * (size_t)HWPROD * NN +
                ((size_t)(gy * WW + gx)) * NN;

    float acc[4][4];

#pragma unroll
    for (int n = 0; n < NN; n++) {
        const __half2* vp = (const __half2*)(sVh + n * NPLANE + a_h * APLANE +
                                             row_h * HSTRIDE + x0);
        float2 f0 = __half22float2(vp[0]);
        float2 f1 = __half22float2(vp[1]);
        float2 f2 = __half22float2(vp[2]);
        float2 f3 = __half22float2(vp[3]);
        float2 f4 = __half22float2(vp[4]);
        float h0 = f0.x, h1 = f0.y, h2 = f1.x, h3 = f1.y;
        float h4 = f2.x, h5 = f2.y, h6 = f3.x, h7 = f3.y;
        float h8 = f4.x, h9 = f4.y;

        const int ai = n & 3;
        acc[0][ai] = fmaf(ua0, h0 + h6, fmaf(ua1, h1 + h5, fmaf(ua2, h2 + h4, ua3 * h3)));
        acc[1][ai] = fmaf(ua0, h1 + h7, fmaf(ua1, h2 + h6, fmaf(ua2, h3 + h5, ua3 * h4)));
        acc[2][ai] = fmaf(ua0, h2 + h8, fmaf(ua1, h3 + h7, fmaf(ua2, h4 + h6, ua3 * h5)));
        acc[3][ai] = fmaf(ua0, h3 + h9, fmaf(ua1, h4 + h8, fmaf(ua2, h5 + h7, ua3 * h6)));

        if (n == 3 || n == 7) {
            const int off = (n == 3) ? 0 : 4;
#pragma unroll
            for (int px = 0; px < 4; px++)
                __stcs((float4*)(op + px * NN + off),
                       make_float4(acc[px][0], acc[px][1], acc[px][2], acc[px][3]));
        }
    }
}

// ---------------------------------------------------------------------------
extern "C" void kernel_launch(void* const* d_in, const int* in_sizes, int n_in,
                              void* d_out, int out_size) {
    (void)in_sizes; (void)n_in; (void)out_size;
    const float* im    = (const float*)d_in[0];  // (512,512,3)
    const float* sig   = (const float*)d_in[1];  // (2,9,9)
    const float* alp   = (const float*)d_in[2];  // (3,7,7)
    const float* binc  = (const float*)d_in[3];  // (8,)
    const float* betas = (const float*)d_in[4];  // (2,)
    float* out = (float*)d_out;                  // (3,2,2,3,512,512,8)

    stage1_kernel<<<dim3(16, 16, CC), 256>>>(im, sig);
    loi_kernel<<<dim3(WW / TW, HH / TH, CC * SS * BB), NTHR>>>(alp, binc, betas, out);
}